// round 1
// baseline (speedup 1.0000x reference)
#include <cuda_runtime.h>
#include <cstdint>

#define BB 2
#define SS 2048
#define DD 1024
#define HH 16
#define HD 64
#define MM (BB*SS)   // 4096

// ---- device scratch (no allocations allowed) ----
__device__ float g_Q[MM*DD];
__device__ float g_K[MM*DD];
__device__ float g_V[MM*DD];
__device__ float g_AO[MM*DD];
__device__ int   g_mask_mode;   // 0 = u8 bytes, 1 = 4-byte words (i32 or f32 bits)

// ---------------------------------------------------------------------------
// Mask dtype sniffing: numpy bool is 1 byte, but the harness may widen bools
// to int32 (or float32). A byte-packed random 0/1 mask read as u32 words is
// astronomically unlikely to have all of its first 256 words in {0,1,0x3F800000}.
// ---------------------------------------------------------------------------
__global__ void detect_mask_kernel(const unsigned int* __restrict__ m) {
    if (threadIdx.x == 0 && blockIdx.x == 0) {
        int wide = 1;
        for (int i = 0; i < 256; i++) {
            unsigned v = m[i];
            if (v != 0u && v != 1u && v != 0x3F800000u) { wide = 0; break; }
        }
        g_mask_mode = wide;
    }
}

// ---------------------------------------------------------------------------
// C[m,n] = sum_k A[m,k]*W[n,k] + bias[n]      (A: MxK rm, W: NxK rm)
// 128x128 block tile, BK=8, 256 threads, 8x8 per thread.
// ---------------------------------------------------------------------------
__global__ __launch_bounds__(256) void gemm_abt(
    const float* __restrict__ A, const float* __restrict__ W,
    const float* __restrict__ bias, float* __restrict__ C,
    int M, int N, int K)
{
    __shared__ float As[8][128];
    __shared__ float Bs[8][128];
    const int tid = threadIdx.x;
    const int m0 = blockIdx.x * 128, n0 = blockIdx.y * 128;
    const int lrow = tid >> 1;           // 0..127
    const int lk   = (tid & 1) * 4;      // 0 or 4
    const int tx = tid & 15, ty = tid >> 4;

    const float* Ap = A + (size_t)(m0 + lrow) * K + lk;
    const float* Wp = W + (size_t)(n0 + lrow) * K + lk;

    float acc[8][8] = {};

    for (int k0 = 0; k0 < K; k0 += 8) {
        float4 av = *(const float4*)(Ap + k0);
        float4 wv = *(const float4*)(Wp + k0);
        __syncthreads();
        As[lk+0][lrow] = av.x; As[lk+1][lrow] = av.y;
        As[lk+2][lrow] = av.z; As[lk+3][lrow] = av.w;
        Bs[lk+0][lrow] = wv.x; Bs[lk+1][lrow] = wv.y;
        Bs[lk+2][lrow] = wv.z; Bs[lk+3][lrow] = wv.w;
        __syncthreads();
        #pragma unroll
        for (int kk = 0; kk < 8; kk++) {
            float4 a0 = *(const float4*)&As[kk][ty*8];
            float4 a1 = *(const float4*)&As[kk][ty*8+4];
            float4 b0 = *(const float4*)&Bs[kk][tx*8];
            float4 b1 = *(const float4*)&Bs[kk][tx*8+4];
            float ar[8] = {a0.x,a0.y,a0.z,a0.w,a1.x,a1.y,a1.z,a1.w};
            float br[8] = {b0.x,b0.y,b0.z,b0.w,b1.x,b1.y,b1.z,b1.w};
            #pragma unroll
            for (int i = 0; i < 8; i++)
                #pragma unroll
                for (int j = 0; j < 8; j++)
                    acc[i][j] += ar[i]*br[j];
        }
    }

    #pragma unroll
    for (int i = 0; i < 8; i++) {
        int m = m0 + ty*8 + i;
        #pragma unroll
        for (int j = 0; j < 8; j += 4) {
            int n = n0 + tx*8 + j;
            float4 o;
            o.x = acc[i][j+0] + bias[n+0];
            o.y = acc[i][j+1] + bias[n+1];
            o.z = acc[i][j+2] + bias[n+2];
            o.w = acc[i][j+3] + bias[n+3];
            *(float4*)&C[(size_t)m*N + n] = o;
        }
    }
}

// ---------------------------------------------------------------------------
// Flash attention, fp32. One block = (b, h, 64-query tile). 256 threads (16x16),
// each thread owns a 4x4 fragment. 64x64 KV tiles, online softmax.
// Smem: Qs + Ks + Vs = 48KB exactly; P tile reuses Ks storage.
// ---------------------------------------------------------------------------
__global__ __launch_bounds__(256) void attn_kernel(
    const float* __restrict__ Qg, const float* __restrict__ Kg,
    const float* __restrict__ Vg, const void* __restrict__ maskp,
    float* __restrict__ Og)
{
    __shared__ float Qs[64][64];   // [d][q]
    __shared__ float Ks[64][64];   // [d][k]  (reused as Ps[q][k])
    __shared__ float Vs[64][64];   // [k][d]
    float (*Ps)[64] = Ks;

    const int tid = threadIdx.x;
    const int tx = tid & 15, ty = tid >> 4;
    const int q0 = blockIdx.x * 64;
    const int h  = blockIdx.y;
    const int b  = blockIdx.z;
    const int wide = g_mask_mode;

    const float* Qbase = Qg + ((size_t)(b*SS + q0))*DD + h*HD;
    const float* Kbase = Kg + ((size_t)b*SS)*DD + h*HD;
    const float* Vbase = Vg + ((size_t)b*SS)*DD + h*HD;
    const uint8_t* mask8  = (const uint8_t*)maskp + (size_t)b*SS*SS;
    const int*     mask32 = (const int*)maskp     + (size_t)b*SS*SS;

    // load Q tile (transposed to [d][q])
    {
        int r  = tid >> 2;
        int d0 = (tid & 3) * 4;
        #pragma unroll
        for (int c = 0; c < 4; c++) {
            int d = d0 + c*16;
            float4 v = *(const float4*)(Qbase + (size_t)r*DD + d);
            Qs[d+0][r]=v.x; Qs[d+1][r]=v.y; Qs[d+2][r]=v.z; Qs[d+3][r]=v.w;
        }
    }

    float m_r[4], l_r[4], acc[4][4];
    #pragma unroll
    for (int i = 0; i < 4; i++) {
        m_r[i] = -1e30f; l_r[i] = 0.f;
        #pragma unroll
        for (int j = 0; j < 4; j++) acc[i][j] = 0.f;
    }

    for (int kv0 = 0; kv0 < SS; kv0 += 64) {
        __syncthreads();  // protect Ks(=Ps)/Vs readers from previous iteration
        {
            int r  = tid >> 2;
            int d0 = (tid & 3) * 4;
            const float* kp = Kbase + (size_t)(kv0 + r)*DD;
            const float* vp = Vbase + (size_t)(kv0 + r)*DD;
            #pragma unroll
            for (int c = 0; c < 4; c++) {
                int d = d0 + c*16;
                float4 kv = *(const float4*)(kp + d);
                Ks[d+0][r]=kv.x; Ks[d+1][r]=kv.y; Ks[d+2][r]=kv.z; Ks[d+3][r]=kv.w;
                *(float4*)&Vs[r][d] = *(const float4*)(vp + d);
            }
        }
        __syncthreads();

        // S = Q K^T (4x4 fragment per thread)
        float s[4][4] = {};
        #pragma unroll 8
        for (int d = 0; d < 64; d++) {
            float4 q4 = *(const float4*)&Qs[d][ty*4];
            float4 k4 = *(const float4*)&Ks[d][tx*4];
            float qa[4] = {q4.x,q4.y,q4.z,q4.w};
            float ka[4] = {k4.x,k4.y,k4.z,k4.w};
            #pragma unroll
            for (int i = 0; i < 4; i++)
                #pragma unroll
                for (int j = 0; j < 4; j++)
                    s[i][j] += qa[i]*ka[j];
        }

        // scale + mask
        #pragma unroll
        for (int i = 0; i < 4; i++) {
            size_t row = (size_t)(q0 + ty*4 + i)*SS + (kv0 + tx*4);
            int mk[4];
            if (wide) {
                int4 mi = *(const int4*)(mask32 + row);
                mk[0]=mi.x; mk[1]=mi.y; mk[2]=mi.z; mk[3]=mi.w;
            } else {
                uchar4 mb = *(const uchar4*)(mask8 + row);
                mk[0]=mb.x; mk[1]=mb.y; mk[2]=mb.z; mk[3]=mb.w;
            }
            #pragma unroll
            for (int j = 0; j < 4; j++)
                s[i][j] = mk[j] ? -1e30f : s[i][j]*0.125f;
        }

        // online softmax update
        #pragma unroll
        for (int i = 0; i < 4; i++) {
            float tmax = fmaxf(fmaxf(s[i][0], s[i][1]), fmaxf(s[i][2], s[i][3]));
            #pragma unroll
            for (int o = 8; o >= 1; o >>= 1)
                tmax = fmaxf(tmax, __shfl_xor_sync(0xffffffffu, tmax, o));
            float m_new = fmaxf(m_r[i], tmax);
            float alpha = __expf(m_r[i] - m_new);
            m_r[i] = m_new;
            float rsum = 0.f;
            #pragma unroll
            for (int j = 0; j < 4; j++) {
                float p = __expf(s[i][j] - m_new);
                s[i][j] = p;
                rsum += p;
            }
            #pragma unroll
            for (int o = 8; o >= 1; o >>= 1)
                rsum += __shfl_xor_sync(0xffffffffu, rsum, o);
            l_r[i] = l_r[i]*alpha + rsum;
            #pragma unroll
            for (int j = 0; j < 4; j++) acc[i][j] *= alpha;
        }

        __syncthreads();  // everyone done reading Ks before overwriting as Ps
        #pragma unroll
        for (int i = 0; i < 4; i++)
            *(float4*)&Ps[ty*4+i][tx*4] = make_float4(s[i][0], s[i][1], s[i][2], s[i][3]);
        __syncthreads();

        // O += P @ V
        #pragma unroll 4
        for (int j = 0; j < 64; j += 4) {
            float4 v0 = *(const float4*)&Vs[j+0][tx*4];
            float4 v1 = *(const float4*)&Vs[j+1][tx*4];
            float4 v2 = *(const float4*)&Vs[j+2][tx*4];
            float4 v3 = *(const float4*)&Vs[j+3][tx*4];
            #pragma unroll
            for (int i = 0; i < 4; i++) {
                float4 p = *(const float4*)&Ps[ty*4+i][j];
                acc[i][0] += p.x*v0.x; acc[i][1] += p.x*v0.y; acc[i][2] += p.x*v0.z; acc[i][3] += p.x*v0.w;
                acc[i][0] += p.y*v1.x; acc[i][1] += p.y*v1.y; acc[i][2] += p.y*v1.z; acc[i][3] += p.y*v1.w;
                acc[i][0] += p.z*v2.x; acc[i][1] += p.z*v2.y; acc[i][2] += p.z*v2.z; acc[i][3] += p.z*v2.w;
                acc[i][0] += p.w*v3.x; acc[i][1] += p.w*v3.y; acc[i][2] += p.w*v3.z; acc[i][3] += p.w*v3.w;
            }
        }
    }

    // epilogue: normalize and store (B,S,D) layout with head offset
    #pragma unroll
    for (int i = 0; i < 4; i++) {
        float inv = 1.0f / l_r[i];
        int q = q0 + ty*4 + i;
        float4 o = make_float4(acc[i][0]*inv, acc[i][1]*inv, acc[i][2]*inv, acc[i][3]*inv);
        *(float4*)&Og[((size_t)(b*SS + q))*DD + h*HD + tx*4] = o;
    }
}

// ---------------------------------------------------------------------------
extern "C" void kernel_launch(void* const* d_in, const int* in_sizes, int n_in,
                              void* d_out, int out_size)
{
    const float* query = (const float*)d_in[0];
    const float* key   = (const float*)d_in[1];
    const float* value = (const float*)d_in[2];
    const void*  mask  = d_in[3];
    const float* Wq = (const float*)d_in[4];
    const float* Wk = (const float*)d_in[5];
    const float* Wv = (const float*)d_in[6];
    const float* Wo = (const float*)d_in[7];
    const float* bq = (const float*)d_in[8];
    const float* bk = (const float*)d_in[9];
    const float* bv = (const float*)d_in[10];
    const float* bo = (const float*)d_in[11];
    float* out = (float*)d_out;

    float *Qp, *Kp, *Vp, *AOp;
    cudaGetSymbolAddress((void**)&Qp,  g_Q);
    cudaGetSymbolAddress((void**)&Kp,  g_K);
    cudaGetSymbolAddress((void**)&Vp,  g_V);
    cudaGetSymbolAddress((void**)&AOp, g_AO);

    detect_mask_kernel<<<1, 32>>>((const unsigned int*)mask);

    dim3 gblk(256);
    dim3 ggrid(MM/128, DD/128);   // (32, 8)
    gemm_abt<<<ggrid, gblk>>>(query, Wq, bq, Qp,  MM, DD, DD);
    gemm_abt<<<ggrid, gblk>>>(key,   Wk, bk, Kp,  MM, DD, DD);
    gemm_abt<<<ggrid, gblk>>>(value, Wv, bv, Vp,  MM, DD, DD);

    dim3 agrid(SS/64, HH, BB);    // (32, 16, 2)
    attn_kernel<<<agrid, 256>>>(Qp, Kp, Vp, mask, AOp);

    gemm_abt<<<ggrid, gblk>>>(AOp, Wo, bo, out, MM, DD, DD);
}

// round 2
// speedup vs baseline: 2.5216x; 2.5216x over previous
#include <cuda_runtime.h>
#include <cstdint>

#define BB 2
#define SS 2048
#define DD 1024
#define HH 16
#define HD 64
#define MM (BB*SS)   // 4096

// ---- device scratch (no allocations allowed) ----
__device__ float g_Q[MM*DD];
__device__ float g_K[MM*DD];
__device__ float g_V[MM*DD];
__device__ float g_AO[MM*DD];
__device__ int   g_mask_mode;   // 0 = u8 bytes, 1 = 4-byte words (i32 or f32 bits)

__device__ __forceinline__ uint32_t f2tf(float x) {
    uint32_t r;
    asm("cvt.rna.tf32.f32 %0, %1;" : "=r"(r) : "f"(x));
    return r;
}
__device__ __forceinline__ float u2f(uint32_t x) { return __uint_as_float(x); }

// D += A(16x8 row) * B(8x8 col) ; tf32 inputs, f32 accum
__device__ __forceinline__ void mma8(float* c, const uint32_t* a, const uint32_t* b) {
    asm volatile(
        "mma.sync.aligned.m16n8k8.row.col.f32.tf32.tf32.f32 "
        "{%0,%1,%2,%3}, {%4,%5,%6,%7}, {%8,%9}, {%0,%1,%2,%3};\n"
        : "+f"(c[0]), "+f"(c[1]), "+f"(c[2]), "+f"(c[3])
        : "r"(a[0]), "r"(a[1]), "r"(a[2]), "r"(a[3]), "r"(b[0]), "r"(b[1]));
}

// ---------------------------------------------------------------------------
// Mask dtype sniffing (bool-as-bytes vs widened 4-byte ints/floats).
// ---------------------------------------------------------------------------
__global__ void detect_mask_kernel(const unsigned int* __restrict__ m) {
    if (threadIdx.x == 0 && blockIdx.x == 0) {
        int wide = 1;
        for (int i = 0; i < 256; i++) {
            unsigned v = m[i];
            if (v != 0u && v != 1u && v != 0x3F800000u) { wide = 0; break; }
        }
        g_mask_mode = wide;
    }
}

// ---------------------------------------------------------------------------
// C[m,n] = sum_k A[m,k]*W[n,k] + bias[n]   via tf32 mma.sync
// Block 128x128, BK=16, 256 threads (8 warps 2x4), warp tile 64x32.
// As/Bs stored [row][k] with stride 20 -> conflict-free fragment LDS.
// ---------------------------------------------------------------------------
__global__ __launch_bounds__(256) void gemm_tf32(
    const float* __restrict__ A, const float* __restrict__ W,
    const float* __restrict__ bias, float* __restrict__ C,
    int M, int N, int K)
{
    __shared__ __align__(16) float As[128][20];
    __shared__ __align__(16) float Bs[128][20];

    const int tid  = threadIdx.x;
    const int lane = tid & 31, wid = tid >> 5;
    const int g = lane >> 2, qq = lane & 3;
    const int wm = (wid & 1) * 64;        // warp m offset
    const int wn = (wid >> 1) * 32;       // warp n offset
    const int m0 = blockIdx.x * 128, n0 = blockIdx.y * 128;

    const int lr = tid >> 2;              // 0..63 (load row)
    const int lc = (tid & 3) * 4;         // 0,4,8,12 (load col)

    float acc[4][4][4];
    #pragma unroll
    for (int i = 0; i < 4; i++)
        #pragma unroll
        for (int j = 0; j < 4; j++)
            #pragma unroll
            for (int r = 0; r < 4; r++) acc[i][j][r] = 0.f;

    const float* Ap = A + (size_t)m0 * K;
    const float* Wp = W + (size_t)n0 * K;

    for (int k0 = 0; k0 < K; k0 += 16) {
        float4 a0 = *(const float4*)(Ap + (size_t)lr      * K + k0 + lc);
        float4 a1 = *(const float4*)(Ap + (size_t)(lr+64) * K + k0 + lc);
        float4 w0 = *(const float4*)(Wp + (size_t)lr      * K + k0 + lc);
        float4 w1 = *(const float4*)(Wp + (size_t)(lr+64) * K + k0 + lc);
        __syncthreads();
        {
            float4 t;
            t.x=u2f(f2tf(a0.x)); t.y=u2f(f2tf(a0.y)); t.z=u2f(f2tf(a0.z)); t.w=u2f(f2tf(a0.w));
            *(float4*)&As[lr][lc] = t;
            t.x=u2f(f2tf(a1.x)); t.y=u2f(f2tf(a1.y)); t.z=u2f(f2tf(a1.z)); t.w=u2f(f2tf(a1.w));
            *(float4*)&As[lr+64][lc] = t;
            t.x=u2f(f2tf(w0.x)); t.y=u2f(f2tf(w0.y)); t.z=u2f(f2tf(w0.z)); t.w=u2f(f2tf(w0.w));
            *(float4*)&Bs[lr][lc] = t;
            t.x=u2f(f2tf(w1.x)); t.y=u2f(f2tf(w1.y)); t.z=u2f(f2tf(w1.z)); t.w=u2f(f2tf(w1.w));
            *(float4*)&Bs[lr+64][lc] = t;
        }
        __syncthreads();

        #pragma unroll
        for (int ks = 0; ks < 2; ks++) {
            const int kb = ks * 8;
            uint32_t aF[4][4], bF[4][2];
            #pragma unroll
            for (int j = 0; j < 4; j++) {
                bF[j][0] = __float_as_uint(Bs[wn + j*8 + g][kb + qq]);
                bF[j][1] = __float_as_uint(Bs[wn + j*8 + g][kb + qq + 4]);
            }
            #pragma unroll
            for (int i = 0; i < 4; i++) {
                aF[i][0] = __float_as_uint(As[wm + i*16 + g    ][kb + qq]);
                aF[i][1] = __float_as_uint(As[wm + i*16 + g + 8][kb + qq]);
                aF[i][2] = __float_as_uint(As[wm + i*16 + g    ][kb + qq + 4]);
                aF[i][3] = __float_as_uint(As[wm + i*16 + g + 8][kb + qq + 4]);
            }
            #pragma unroll
            for (int i = 0; i < 4; i++)
                #pragma unroll
                for (int j = 0; j < 4; j++)
                    mma8(acc[i][j], aF[i], bF[j]);
        }
    }

    // epilogue: bias + store (float2: cols 2q,2q+1)
    #pragma unroll
    for (int j = 0; j < 4; j++) {
        const int col = n0 + wn + j*8 + 2*qq;
        const float2 bv = *(const float2*)&bias[col];
        #pragma unroll
        for (int i = 0; i < 4; i++) {
            const int row = m0 + wm + i*16 + g;
            float2 o0 = make_float2(acc[i][j][0] + bv.x, acc[i][j][1] + bv.y);
            float2 o1 = make_float2(acc[i][j][2] + bv.x, acc[i][j][3] + bv.y);
            *(float2*)&C[(size_t)row     * N + col] = o0;
            *(float2*)&C[(size_t)(row+8) * N + col] = o1;
        }
    }
}

// ---------------------------------------------------------------------------
// Flash attention with tf32 mma.sync.
// Block = (b, h, 64-query tile), 128 threads (4 warps), warp = 16 q rows.
// KV tiles 64x64. Ks[kv][d] stride 68 (reused as Ps[q][kv]); Vs[kv][d] stride 72.
// Q fragments held in registers (pre-scaled by 1/8, tf32-rounded).
// ---------------------------------------------------------------------------
__global__ __launch_bounds__(128) void attn_tf32(
    const float* __restrict__ Qg, const float* __restrict__ Kg,
    const float* __restrict__ Vg, const void* __restrict__ maskp,
    float* __restrict__ Og)
{
    __shared__ __align__(16) float Ks[64][68];   // K tile; later P tile
    __shared__ __align__(16) float Vs[64][72];   // V tile
    float (*Ps)[68] = Ks;

    const int tid  = threadIdx.x;
    const int lane = tid & 31, wid = tid >> 5;
    const int g = lane >> 2, qq = lane & 3;
    const int qb = wid * 16;
    const int q0 = blockIdx.x * 64, h = blockIdx.y, b = blockIdx.z;
    const int wide = g_mask_mode;

    const float* Qbase = Qg + ((size_t)(b*SS + q0))*DD + h*HD;
    const float* Kbase = Kg + ((size_t)b*SS)*DD + h*HD;
    const float* Vbase = Vg + ((size_t)b*SS)*DD + h*HD;
    const uint8_t* mask8  = (const uint8_t*)maskp + (size_t)b*SS*SS;
    const int*     mask32 = (const int*)maskp     + (size_t)b*SS*SS;

    const int r0 = qb + g;        // local q row (first)
    const int r1 = qb + g + 8;    // local q row (second)

    // Q fragments: 8 k-tiles of d, scaled by 1/sqrt(64)=0.125
    uint32_t aQ[8][4];
    #pragma unroll
    for (int kt = 0; kt < 8; kt++) {
        const int d0 = kt * 8;
        aQ[kt][0] = f2tf(0.125f * Qbase[(size_t)r0*DD + d0 + qq]);
        aQ[kt][1] = f2tf(0.125f * Qbase[(size_t)r1*DD + d0 + qq]);
        aQ[kt][2] = f2tf(0.125f * Qbase[(size_t)r0*DD + d0 + qq + 4]);
        aQ[kt][3] = f2tf(0.125f * Qbase[(size_t)r1*DD + d0 + qq + 4]);
    }

    float oacc[8][4];
    #pragma unroll
    for (int j = 0; j < 8; j++)
        #pragma unroll
        for (int r = 0; r < 4; r++) oacc[j][r] = 0.f;
    float m0r = -1e30f, m1r = -1e30f, l0 = 0.f, l1 = 0.f;

    const int lr = tid >> 4;          // 0..7
    const int lc = (tid & 15) * 4;    // 0..60

    for (int kv0 = 0; kv0 < SS; kv0 += 64) {
        __syncthreads();   // previous PV reads of Ps/Vs complete
        #pragma unroll
        for (int rr = 0; rr < 8; rr++) {
            const int kv = rr*8 + lr;
            float4 k4 = *(const float4*)(Kbase + (size_t)(kv0+kv)*DD + lc);
            float4 v4 = *(const float4*)(Vbase + (size_t)(kv0+kv)*DD + lc);
            float4 t;
            t.x=u2f(f2tf(k4.x)); t.y=u2f(f2tf(k4.y)); t.z=u2f(f2tf(k4.z)); t.w=u2f(f2tf(k4.w));
            *(float4*)&Ks[kv][lc] = t;
            t.x=u2f(f2tf(v4.x)); t.y=u2f(f2tf(v4.y)); t.z=u2f(f2tf(v4.z)); t.w=u2f(f2tf(v4.w));
            *(float4*)&Vs[kv][lc] = t;
        }
        __syncthreads();

        // S = Q K^T  (per warp: 16 q rows x 64 kv)
        float sacc[8][4];
        #pragma unroll
        for (int j = 0; j < 8; j++)
            #pragma unroll
            for (int r = 0; r < 4; r++) sacc[j][r] = 0.f;

        #pragma unroll
        for (int kt = 0; kt < 8; kt++) {
            #pragma unroll
            for (int j = 0; j < 8; j++) {
                uint32_t bv[2];
                bv[0] = __float_as_uint(Ks[j*8 + g][kt*8 + qq]);
                bv[1] = __float_as_uint(Ks[j*8 + g][kt*8 + qq + 4]);
                mma8(sacc[j], aQ[kt], bv);
            }
        }

        // mask
        #pragma unroll
        for (int j = 0; j < 8; j++) {
            const int col = kv0 + j*8 + 2*qq;
            if (wide) {
                int2 mA = *(const int2*)(mask32 + (size_t)(q0+r0)*SS + col);
                int2 mB = *(const int2*)(mask32 + (size_t)(q0+r1)*SS + col);
                if (mA.x) sacc[j][0] = -1e30f;
                if (mA.y) sacc[j][1] = -1e30f;
                if (mB.x) sacc[j][2] = -1e30f;
                if (mB.y) sacc[j][3] = -1e30f;
            } else {
                unsigned mA = *(const unsigned short*)(mask8 + (size_t)(q0+r0)*SS + col);
                unsigned mB = *(const unsigned short*)(mask8 + (size_t)(q0+r1)*SS + col);
                if (mA & 0xFFu) sacc[j][0] = -1e30f;
                if (mA >> 8)    sacc[j][1] = -1e30f;
                if (mB & 0xFFu) sacc[j][2] = -1e30f;
                if (mB >> 8)    sacc[j][3] = -1e30f;
            }
        }

        // online softmax (row r0 uses regs 0,1; row r1 uses 2,3); quad reduce
        float mx0 = -1e30f, mx1 = -1e30f;
        #pragma unroll
        for (int j = 0; j < 8; j++) {
            mx0 = fmaxf(mx0, fmaxf(sacc[j][0], sacc[j][1]));
            mx1 = fmaxf(mx1, fmaxf(sacc[j][2], sacc[j][3]));
        }
        mx0 = fmaxf(mx0, __shfl_xor_sync(0xffffffffu, mx0, 1));
        mx0 = fmaxf(mx0, __shfl_xor_sync(0xffffffffu, mx0, 2));
        mx1 = fmaxf(mx1, __shfl_xor_sync(0xffffffffu, mx1, 1));
        mx1 = fmaxf(mx1, __shfl_xor_sync(0xffffffffu, mx1, 2));

        const float mn0 = fmaxf(m0r, mx0), mn1 = fmaxf(m1r, mx1);
        const float al0 = __expf(m0r - mn0), al1 = __expf(m1r - mn1);
        m0r = mn0; m1r = mn1;

        float s0 = 0.f, s1 = 0.f;
        #pragma unroll
        for (int j = 0; j < 8; j++) {
            float p0 = __expf(sacc[j][0] - mn0);
            float p1 = __expf(sacc[j][1] - mn0);
            float p2 = __expf(sacc[j][2] - mn1);
            float p3 = __expf(sacc[j][3] - mn1);
            sacc[j][0] = p0; sacc[j][1] = p1; sacc[j][2] = p2; sacc[j][3] = p3;
            s0 += p0 + p1; s1 += p2 + p3;
        }
        s0 += __shfl_xor_sync(0xffffffffu, s0, 1);
        s0 += __shfl_xor_sync(0xffffffffu, s0, 2);
        s1 += __shfl_xor_sync(0xffffffffu, s1, 1);
        s1 += __shfl_xor_sync(0xffffffffu, s1, 2);
        l0 = l0*al0 + s0;
        l1 = l1*al1 + s1;
        #pragma unroll
        for (int j = 0; j < 8; j++) {
            oacc[j][0] *= al0; oacc[j][1] *= al0;
            oacc[j][2] *= al1; oacc[j][3] *= al1;
        }

        __syncthreads();   // all warps done reading Ks before overwrite as Ps
        #pragma unroll
        for (int j = 0; j < 8; j++) {
            *(float2*)&Ps[r0][j*8 + 2*qq] =
                make_float2(u2f(f2tf(sacc[j][0])), u2f(f2tf(sacc[j][1])));
            *(float2*)&Ps[r1][j*8 + 2*qq] =
                make_float2(u2f(f2tf(sacc[j][2])), u2f(f2tf(sacc[j][3])));
        }
        __syncthreads();

        // O += P @ V
        #pragma unroll
        for (int kt = 0; kt < 8; kt++) {
            uint32_t aP[4];
            aP[0] = __float_as_uint(Ps[r0][kt*8 + qq]);
            aP[1] = __float_as_uint(Ps[r1][kt*8 + qq]);
            aP[2] = __float_as_uint(Ps[r0][kt*8 + qq + 4]);
            aP[3] = __float_as_uint(Ps[r1][kt*8 + qq + 4]);
            #pragma unroll
            for (int j = 0; j < 8; j++) {
                uint32_t bv[2];
                bv[0] = __float_as_uint(Vs[kt*8 + qq    ][j*8 + g]);
                bv[1] = __float_as_uint(Vs[kt*8 + qq + 4][j*8 + g]);
                mma8(oacc[j], aP, bv);
            }
        }
    }

    // epilogue
    const float inv0 = 1.0f / l0, inv1 = 1.0f / l1;
    #pragma unroll
    for (int j = 0; j < 8; j++) {
        *(float2*)&Og[((size_t)(b*SS + q0 + r0))*DD + h*HD + j*8 + 2*qq] =
            make_float2(oacc[j][0]*inv0, oacc[j][1]*inv0);
        *(float2*)&Og[((size_t)(b*SS + q0 + r1))*DD + h*HD + j*8 + 2*qq] =
            make_float2(oacc[j][2]*inv1, oacc[j][3]*inv1);
    }
}

// ---------------------------------------------------------------------------
extern "C" void kernel_launch(void* const* d_in, const int* in_sizes, int n_in,
                              void* d_out, int out_size)
{
    const float* query = (const float*)d_in[0];
    const float* key   = (const float*)d_in[1];
    const float* value = (const float*)d_in[2];
    const void*  mask  = d_in[3];
    const float* Wq = (const float*)d_in[4];
    const float* Wk = (const float*)d_in[5];
    const float* Wv = (const float*)d_in[6];
    const float* Wo = (const float*)d_in[7];
    const float* bq = (const float*)d_in[8];
    const float* bk = (const float*)d_in[9];
    const float* bv = (const float*)d_in[10];
    const float* bo = (const float*)d_in[11];
    float* out = (float*)d_out;

    float *Qp, *Kp, *Vp, *AOp;
    cudaGetSymbolAddress((void**)&Qp,  g_Q);
    cudaGetSymbolAddress((void**)&Kp,  g_K);
    cudaGetSymbolAddress((void**)&Vp,  g_V);
    cudaGetSymbolAddress((void**)&AOp, g_AO);

    detect_mask_kernel<<<1, 32>>>((const unsigned int*)mask);

    dim3 ggrid(MM/128, DD/128);   // (32, 8)
    gemm_tf32<<<ggrid, 256>>>(query, Wq, bq, Qp,  MM, DD, DD);
    gemm_tf32<<<ggrid, 256>>>(key,   Wk, bk, Kp,  MM, DD, DD);
    gemm_tf32<<<ggrid, 256>>>(value, Wv, bv, Vp,  MM, DD, DD);

    dim3 agrid(SS/64, HH, BB);    // (32, 16, 2)
    attn_tf32<<<agrid, 128>>>(Qp, Kp, Vp, mask, AOp);

    gemm_tf32<<<ggrid, 256>>>(AOp, Wo, bo, out, MM, DD, DD);
}